// round 1
// baseline (speedup 1.0000x reference)
#include <cuda_runtime.h>
#include <cuda_bf16.h>

// ---------------------------------------------------------------------------
// SpatialEncoder: bi-level routing attention, fp32 baseline.
// Pipeline (per launch):
//  1. k_qkv_gemm   x{1,2} @ Wqkv^T + b  -> g_qkv[b]  (window-major tokens, 768ch)
//  2. k_pool       4x4-pooled kv tokens + window means (qwin/kwin)
//  3. k_route      64x64 routing logits, diag=1, top-4 -> g_idx
//  4. k_attend     per (window, head): softmax(q k^T * s) v  -> g_att (image NHWC)
//  5. k_lepe       depthwise 3x3 over cross-branch V, += g_att
//  6. k_proj       g_att @ Wo^T + bo -> d_out
// ---------------------------------------------------------------------------

#define NB    4
#define HH    128
#define WW    128
#define DIM   256
#define QK    256
#define CKV   512
#define QKVC  768
#define NW    8
#define HWIN  16
#define P2    64
#define W2    256
#define KVW   4
#define W2KV  16
#define TOPK  4
#define HEADS 8
#define DH    32
#define TOK   (NB*P2*W2)          // 65536 window-major tokens
#define SCALEF 0.0625f            // 256^-0.5

// -------- scratch (device globals; allocation APIs are forbidden) ----------
__device__ float g_qkv [2][(size_t)TOK*QKVC];       // 2 x 201 MB
__device__ float g_pool[2][NB*P2*W2KV*CKV];         // 2 x 8.4 MB
__device__ float g_qwin[2][NB*P2*QK];
__device__ float g_kwin[2][NB*P2*QK];
__device__ int   g_idx [2][NB*P2*TOPK];
__device__ float g_att [2][(size_t)NB*HH*WW*DIM];   // 2 x 64 MB, image NHWC

// ------------------------------- QKV GEMM ----------------------------------
// C[t][j] = sum_c X[tok(t)][c] * Wqkv[j][c] + b[j]
// M=65536 (window-major tokens), N=768, K=256.  BM=BN=128, BK=8, 8x8 microtile.
__global__ __launch_bounds__(256) void k_qkv_gemm(
    const float* __restrict__ X, const float* __restrict__ Wq,
    const float* __restrict__ bq, int b)
{
    __shared__ float As[8][132];
    __shared__ float Bs[8][132];
    const int tid = threadIdx.x;
    const int tx = tid & 15, ty = tid >> 4;
    const int t0  = blockIdx.y * 128;
    const int jn0 = blockIdx.x * 128;

    // A loader: window-major token -> image NHWC address
    const int am  = tid >> 1;                 // 0..127 (token within tile)
    const int lk  = (tid & 1) << 2;           // 0 or 4
    {
        // nothing: pointers computed below
    }
    const int ltok = t0 + am;
    const int n   = ltok >> 14;
    const int r   = ltok & 16383;
    const int win = r >> 8;
    const int pix = r & 255;
    const int h   = ((win >> 3) << 4) | (pix >> 4);
    const int w   = ((win & 7)  << 4) | (pix & 15);
    const float* ap = X + ((size_t)(((n << 7) + h) << 7) + w) * DIM + lk;
    const float* bp = Wq + (size_t)(jn0 + am) * 256 + lk;

    float acc[8][8];
    #pragma unroll
    for (int i = 0; i < 8; i++)
        #pragma unroll
        for (int j = 0; j < 8; j++) acc[i][j] = 0.f;

    for (int k0 = 0; k0 < 256; k0 += 8) {
        float4 av = *(const float4*)(ap + k0);
        float4 bv = *(const float4*)(bp + k0);
        As[lk+0][am] = av.x; As[lk+1][am] = av.y; As[lk+2][am] = av.z; As[lk+3][am] = av.w;
        Bs[lk+0][am] = bv.x; Bs[lk+1][am] = bv.y; Bs[lk+2][am] = bv.z; Bs[lk+3][am] = bv.w;
        __syncthreads();
        #pragma unroll
        for (int kk = 0; kk < 8; kk++) {
            float a[8], bb[8];
            *(float4*)&a[0]  = *(const float4*)&As[kk][ty*8];
            *(float4*)&a[4]  = *(const float4*)&As[kk][ty*8+4];
            *(float4*)&bb[0] = *(const float4*)&Bs[kk][tx*8];
            *(float4*)&bb[4] = *(const float4*)&Bs[kk][tx*8+4];
            #pragma unroll
            for (int i = 0; i < 8; i++)
                #pragma unroll
                for (int j = 0; j < 8; j++)
                    acc[i][j] += a[i] * bb[j];
        }
        __syncthreads();
    }
    float* outp = g_qkv[b];
    #pragma unroll
    for (int i = 0; i < 8; i++) {
        const size_t t = (size_t)(t0 + ty*8 + i);
        #pragma unroll
        for (int j = 0; j < 8; j++) {
            const int col = jn0 + tx*8 + j;
            outp[t*QKVC + col] = acc[i][j] + bq[col];
        }
    }
}

// ------------------------------ pooling ------------------------------------
__global__ __launch_bounds__(256) void k_pool(int b)
{
    const int nwin = blockIdx.x;                    // n*64+win
    const int tid = threadIdx.x;
    const float* base = g_qkv[b] + (size_t)nwin * W2 * QKVC;

    float qs = 0.f, ks = 0.f;
    for (int p = 0; p < W2; p++) {
        qs += base[(size_t)p*QKVC + tid];
        ks += base[(size_t)p*QKVC + QK + tid];
    }
    g_qwin[b][nwin*QK + tid] = qs * (1.f/256.f);
    g_kwin[b][nwin*QK + tid] = ks * (1.f/256.f);

    for (int e = tid; e < W2KV*CKV; e += 256) {
        const int s  = e >> 9;
        const int cc = e & 511;
        const int py0 = (s >> 2) << 2, px0 = (s & 3) << 2;
        float acc = 0.f;
        #pragma unroll
        for (int i = 0; i < 4; i++)
            #pragma unroll
            for (int j = 0; j < 4; j++)
                acc += base[(size_t)((py0+i)*16 + px0+j)*QKVC + QK + cc];
        g_pool[b][(size_t)(nwin*W2KV + s)*CKV + cc] = acc * (1.f/16.f);
    }
}

// ------------------------------ routing ------------------------------------
__global__ void k_route(int qb, int kb, int ib)
{
    const int i = blockIdx.x;      // query window
    const int n = blockIdx.y;
    const int j = threadIdx.x;     // 0..63
    const float* qp = g_qwin[qb] + (size_t)(n*P2 + i)*QK;
    const float* kp = g_kwin[kb] + (size_t)(n*P2 + j)*QK;
    float s = 0.f;
    for (int c = 0; c < QK; c++) s += qp[c]*kp[c];
    s *= SCALEF;
    if (j == i) s = 1.0f;
    __shared__ float lg[P2];
    lg[j] = s;
    __syncthreads();
    if (j == 0) {
        #pragma unroll
        for (int t = 0; t < TOPK; t++) {
            float best = -1e30f; int bi = 0;
            for (int u = 0; u < P2; u++)
                if (lg[u] > best) { best = lg[u]; bi = u; }   // strict > = jax tie-break
            g_idx[ib][(n*P2 + i)*TOPK + t] = bi;
            lg[bi] = -1e30f;
        }
    }
}

// ----------------------------- attention -----------------------------------
// one block per (window, head); thread = query pixel; 64 gathered KV tokens.
__global__ __launch_bounds__(256) void k_attend(int qb, int kvb, int ib, int ob)
{
    const int nwin = blockIdx.x;             // n*64+win
    const int head = blockIdx.y;
    const int n   = nwin >> 6;
    const int win = nwin & 63;
    const int tid = threadIdx.x;

    __shared__ float ks[64][33];
    __shared__ float vs[64][33];
    __shared__ int sel[TOPK];
    if (tid < TOPK) sel[tid] = g_idx[ib][nwin*TOPK + tid];
    __syncthreads();

    for (int e = tid; e < 64*32; e += 256) {
        const int tkn = e >> 5, c = e & 31;
        const int sw  = sel[tkn >> 4];
        const float* pp = g_pool[kvb] + (size_t)((n*P2 + sw)*W2KV + (tkn & 15))*CKV;
        ks[tkn][c] = pp[head*DH + c];
        vs[tkn][c] = pp[QK + head*DH + c];
    }
    __syncthreads();

    const int pix = tid;
    const float* qp = g_qkv[qb] + (size_t)(nwin*W2 + pix)*QKVC + head*DH;
    float q[DH];
    #pragma unroll
    for (int c = 0; c < DH; c++) q[c] = qp[c] * SCALEF;

    float lg[64];
    float mx = -1e30f;
    #pragma unroll
    for (int t = 0; t < 64; t++) {
        float s = 0.f;
        #pragma unroll
        for (int c = 0; c < DH; c++) s += q[c] * ks[t][c];
        lg[t] = s;
        mx = fmaxf(mx, s);
    }
    float den = 0.f;
    #pragma unroll
    for (int t = 0; t < 64; t++) { lg[t] = expf(lg[t] - mx); den += lg[t]; }
    const float inv = 1.f / den;

    float o[DH];
    #pragma unroll
    for (int c = 0; c < DH; c++) o[c] = 0.f;
    #pragma unroll
    for (int t = 0; t < 64; t++) {
        const float p = lg[t];
        #pragma unroll
        for (int c = 0; c < DH; c++) o[c] += p * vs[t][c];
    }

    const int h = ((win >> 3) << 4) | (pix >> 4);
    const int w = ((win & 7)  << 4) | (pix & 15);
    float* op = g_att[ob] + (size_t)(((n << 7) + h)*WW + w)*DIM + head*DH;
    #pragma unroll
    for (int c = 0; c < DH; c++) op[c] = o[c] * inv;
}

// --------------------------- lepe (depthwise 3x3) --------------------------
__global__ __launch_bounds__(256) void k_lepe(int vb, int ob,
    const float* __restrict__ lw, const float* __restrict__ lb)
{
    __shared__ float sw[DIM*9];
    const int p = blockIdx.x;                 // n*16384 + h*128 + w
    const int c = threadIdx.x;                // channel
    for (int e = c; e < DIM*9; e += 256) sw[e] = lw[e];
    __syncthreads();

    const int n  = p >> 14;
    const int hw = p & 16383;
    const int h  = hw >> 7;
    const int w  = hw & 127;

    float acc = g_att[ob][(size_t)p*DIM + c] + lb[c];
    #pragma unroll
    for (int dy = 0; dy < 3; dy++) {
        const int hh = h + dy - 1;
        if ((unsigned)hh >= (unsigned)HH) continue;
        #pragma unroll
        for (int dx = 0; dx < 3; dx++) {
            const int ww2 = w + dx - 1;
            if ((unsigned)ww2 >= (unsigned)WW) continue;
            const int win = ((hh >> 4) << 3) | (ww2 >> 4);
            const int pix = ((hh & 15) << 4) | (ww2 & 15);
            const float v = g_qkv[vb][(size_t)(((n << 6) | win)*W2 + pix)*QKVC + CKV + c];
            acc += v * sw[c*9 + dy*3 + dx];
        }
    }
    g_att[ob][(size_t)p*DIM + c] = acc;
}

// ----------------------------- output proj ---------------------------------
__global__ __launch_bounds__(256) void k_proj(int ob,
    const float* __restrict__ Wo, const float* __restrict__ bo,
    float* __restrict__ out)
{
    __shared__ float As[8][132];
    __shared__ float Bs[8][132];
    const int tid = threadIdx.x;
    const int tx = tid & 15, ty = tid >> 4;
    const int t0  = blockIdx.y * 128;
    const int jn0 = blockIdx.x * 128;

    const int am = tid >> 1;
    const int lk = (tid & 1) << 2;
    const float* ap = g_att[ob] + (size_t)(t0 + am) * DIM + lk;
    const float* bp = Wo + (size_t)(jn0 + am) * DIM + lk;

    float acc[8][8];
    #pragma unroll
    for (int i = 0; i < 8; i++)
        #pragma unroll
        for (int j = 0; j < 8; j++) acc[i][j] = 0.f;

    for (int k0 = 0; k0 < 256; k0 += 8) {
        float4 av = *(const float4*)(ap + k0);
        float4 bv = *(const float4*)(bp + k0);
        As[lk+0][am] = av.x; As[lk+1][am] = av.y; As[lk+2][am] = av.z; As[lk+3][am] = av.w;
        Bs[lk+0][am] = bv.x; Bs[lk+1][am] = bv.y; Bs[lk+2][am] = bv.z; Bs[lk+3][am] = bv.w;
        __syncthreads();
        #pragma unroll
        for (int kk = 0; kk < 8; kk++) {
            float a[8], bb[8];
            *(float4*)&a[0]  = *(const float4*)&As[kk][ty*8];
            *(float4*)&a[4]  = *(const float4*)&As[kk][ty*8+4];
            *(float4*)&bb[0] = *(const float4*)&Bs[kk][tx*8];
            *(float4*)&bb[4] = *(const float4*)&Bs[kk][tx*8+4];
            #pragma unroll
            for (int i = 0; i < 8; i++)
                #pragma unroll
                for (int j = 0; j < 8; j++)
                    acc[i][j] += a[i] * bb[j];
        }
        __syncthreads();
    }
    #pragma unroll
    for (int i = 0; i < 8; i++) {
        const size_t t = (size_t)(t0 + ty*8 + i);
        #pragma unroll
        for (int j = 0; j < 8; j++) {
            const int col = jn0 + tx*8 + j;
            out[t*DIM + col] = acc[i][j] + bo[col];
        }
    }
}

// ------------------------------- launch ------------------------------------
extern "C" void kernel_launch(void* const* d_in, const int* in_sizes, int n_in,
                              void* d_out, int out_size)
{
    const float* x1   = (const float*)d_in[0];
    const float* x2   = (const float*)d_in[1];
    const float* Wqkv = (const float*)d_in[2];
    const float* bqkv = (const float*)d_in[3];
    const float* lw   = (const float*)d_in[4];
    const float* lb   = (const float*)d_in[5];
    const float* Wo   = (const float*)d_in[6];
    const float* bo   = (const float*)d_in[7];
    float* out = (float*)d_out;

    const dim3 gq(QKVC/128, TOK/128);   // (6, 512)
    k_qkv_gemm<<<gq, 256>>>(x1, Wqkv, bqkv, 0);
    k_qkv_gemm<<<gq, 256>>>(x2, Wqkv, bqkv, 1);

    k_pool<<<NB*P2, 256>>>(0);
    k_pool<<<NB*P2, 256>>>(1);

    // idx1 = route(q2w, k1w), idx2 = route(q1w, k2w)
    k_route<<<dim3(P2, NB), 64>>>(1, 0, 0);
    k_route<<<dim3(P2, NB), 64>>>(0, 1, 1);

    // out1 = attend(q2, kv1, idx1), out2 = attend(q1, kv2, idx2)
    k_attend<<<dim3(NB*P2, HEADS), 256>>>(1, 0, 0, 0);
    k_attend<<<dim3(NB*P2, HEADS), 256>>>(0, 1, 1, 1);

    // out1 += lepe(v1), out2 += lepe(v2)
    k_lepe<<<NB*HH*WW, 256>>>(0, 0, lw, lb);
    k_lepe<<<NB*HH*WW, 256>>>(1, 1, lw, lb);

    const dim3 gp(DIM/128, TOK/128);    // (2, 512)
    const size_t half = (size_t)NB*HH*WW*DIM;   // 16777216
    k_proj<<<gp, 256>>>(0, Wo, bo, out);
    k_proj<<<gp, 256>>>(1, Wo, bo, out + half);
}

// round 2
// speedup vs baseline: 1.1034x; 1.1034x over previous
#include <cuda_runtime.h>
#include <cuda_bf16.h>

// ---------------------------------------------------------------------------
// SpatialEncoder: bi-level routing attention, fp32 + packed f32x2 (FFMA2).
// ---------------------------------------------------------------------------

#define NB    4
#define HH    128
#define WW    128
#define DIM   256
#define QK    256
#define CKV   512
#define QKVC  768
#define NW    8
#define HWIN  16
#define P2    64
#define W2    256
#define KVW   4
#define W2KV  16
#define TOPK  4
#define HEADS 8
#define DH    32
#define TOK   (NB*P2*W2)          // 65536 window-major tokens
#define SCALEF 0.0625f            // 256^-0.5

typedef unsigned long long u64;

// ---- packed f32x2 helpers (SASS FFMA2 path; ptxas never emits from C++) ----
__device__ __forceinline__ u64 pack2(float x, float y){
    u64 r; asm("mov.b64 %0,{%1,%2};" : "=l"(r) : "f"(x), "f"(y)); return r;
}
__device__ __forceinline__ u64 dup2(float x){
    u64 r; asm("mov.b64 %0,{%1,%1};" : "=l"(r) : "f"(x)); return r;
}
__device__ __forceinline__ void fma2(u64 &a, u64 b, u64 c){
    asm("fma.rn.f32x2 %0,%1,%2,%0;" : "+l"(a) : "l"(b), "l"(c));
}
__device__ __forceinline__ u64 add2(u64 a, u64 b){
    u64 r; asm("add.rn.f32x2 %0,%1,%2;" : "=l"(r) : "l"(a), "l"(b)); return r;
}
__device__ __forceinline__ u64 mul2(u64 a, u64 b){
    u64 r; asm("mul.rn.f32x2 %0,%1,%2;" : "=l"(r) : "l"(a), "l"(b)); return r;
}
__device__ __forceinline__ float2 unp2(u64 v){
    float lo, hi; asm("mov.b64 {%0,%1},%2;" : "=f"(lo), "=f"(hi) : "l"(v));
    return make_float2(lo, hi);
}

// -------- scratch (device globals; allocation APIs are forbidden) ----------
__device__ float g_qkv [2][(size_t)TOK*QKVC];       // 2 x 201 MB
__device__ float g_pool[2][NB*P2*W2KV*CKV];         // 2 x 8.4 MB
__device__ float g_qwin[2][NB*P2*QK];
__device__ float g_kwin[2][NB*P2*QK];
__device__ int   g_idx [2][NB*P2*TOPK];
__device__ float g_att [2][(size_t)NB*HH*WW*DIM];   // 2 x 64 MB, image NHWC

// ------------------------------- QKV GEMM ----------------------------------
// C[t][j] = sum_c X[tok(t)][c] * Wqkv[j][c] + b[j]
// M=65536, N=768, K=256.  BM=BN=128, BK=8, 8x8 microtile, packed f32x2.
__global__ __launch_bounds__(256) void k_qkv_gemm(
    const float* __restrict__ X, const float* __restrict__ Wq,
    const float* __restrict__ bq, int b)
{
    __shared__ float As[8][132];   // 132*4 = 528 B row stride (16B multiple)
    __shared__ float Bs[8][132];
    const int tid = threadIdx.x;
    const int tx = tid & 15, ty = tid >> 4;
    const int t0  = blockIdx.y * 128;
    const int jn0 = blockIdx.x * 128;

    const int am  = tid >> 1;                 // 0..127
    const int lk  = (tid & 1) << 2;           // 0 or 4
    const int ltok = t0 + am;
    const int n   = ltok >> 14;
    const int r   = ltok & 16383;
    const int win = r >> 8;
    const int pix = r & 255;
    const int h   = ((win >> 3) << 4) | (pix >> 4);
    const int w   = ((win & 7)  << 4) | (pix & 15);
    const float* ap = X + ((size_t)(((n << 7) + h) << 7) + w) * DIM + lk;
    const float* bp = Wq + (size_t)(jn0 + am) * 256 + lk;

    u64 acc[8][4];
    #pragma unroll
    for (int i = 0; i < 8; i++)
        #pragma unroll
        for (int j = 0; j < 4; j++) acc[i][j] = 0ull;

    for (int k0 = 0; k0 < 256; k0 += 8) {
        float4 av = *(const float4*)(ap + k0);
        float4 bv = *(const float4*)(bp + k0);
        As[lk+0][am] = av.x; As[lk+1][am] = av.y; As[lk+2][am] = av.z; As[lk+3][am] = av.w;
        Bs[lk+0][am] = bv.x; Bs[lk+1][am] = bv.y; Bs[lk+2][am] = bv.z; Bs[lk+3][am] = bv.w;
        __syncthreads();
        #pragma unroll
        for (int kk = 0; kk < 8; kk++) {
            float a[8];
            *(float4*)&a[0] = *(const float4*)&As[kk][ty*8];
            *(float4*)&a[4] = *(const float4*)&As[kk][ty*8+4];
            const u64* br = (const u64*)&Bs[kk][tx*8];
            const u64 b0 = br[0], b1 = br[1], b2 = br[2], b3 = br[3];
            #pragma unroll
            for (int i = 0; i < 8; i++) {
                const u64 ad = dup2(a[i]);
                fma2(acc[i][0], ad, b0);
                fma2(acc[i][1], ad, b1);
                fma2(acc[i][2], ad, b2);
                fma2(acc[i][3], ad, b3);
            }
        }
        __syncthreads();
    }
    float* outp = g_qkv[b];
    u64 bias[4];
    #pragma unroll
    for (int j = 0; j < 4; j++) {
        const int col = jn0 + tx*8 + j*2;
        bias[j] = pack2(bq[col], bq[col+1]);
    }
    #pragma unroll
    for (int i = 0; i < 8; i++) {
        const size_t t = (size_t)(t0 + ty*8 + i);
        #pragma unroll
        for (int j = 0; j < 4; j++) {
            const int col = jn0 + tx*8 + j*2;
            *(u64*)(outp + t*QKVC + col) = add2(acc[i][j], bias[j]);
        }
    }
}

// ------------------------------ pooling ------------------------------------
__global__ __launch_bounds__(256) void k_pool(int b)
{
    const int nwin = blockIdx.x;                    // n*64+win
    const int tid = threadIdx.x;
    const float* base = g_qkv[b] + (size_t)nwin * W2 * QKVC;

    float qs = 0.f, ks = 0.f;
    for (int p = 0; p < W2; p++) {
        qs += base[(size_t)p*QKVC + tid];
        ks += base[(size_t)p*QKVC + QK + tid];
    }
    g_qwin[b][nwin*QK + tid] = qs * (1.f/256.f);
    g_kwin[b][nwin*QK + tid] = ks * (1.f/256.f);

    for (int e = tid; e < W2KV*CKV; e += 256) {
        const int s  = e >> 9;
        const int cc = e & 511;
        const int py0 = (s >> 2) << 2, px0 = (s & 3) << 2;
        float acc = 0.f;
        #pragma unroll
        for (int i = 0; i < 4; i++)
            #pragma unroll
            for (int j = 0; j < 4; j++)
                acc += base[(size_t)((py0+i)*16 + px0+j)*QKVC + QK + cc];
        g_pool[b][(size_t)(nwin*W2KV + s)*CKV + cc] = acc * (1.f/16.f);
    }
}

// ------------------------------ routing ------------------------------------
__global__ void k_route(int qb, int kb, int ib)
{
    const int i = blockIdx.x;      // query window
    const int n = blockIdx.y;
    const int j = threadIdx.x;     // 0..63
    const float* qp = g_qwin[qb] + (size_t)(n*P2 + i)*QK;
    const float* kp = g_kwin[kb] + (size_t)(n*P2 + j)*QK;
    float s = 0.f;
    for (int c = 0; c < QK; c++) s += qp[c]*kp[c];
    s *= SCALEF;
    if (j == i) s = 1.0f;
    __shared__ float lg[P2];
    lg[j] = s;
    __syncthreads();
    if (j == 0) {
        #pragma unroll
        for (int t = 0; t < TOPK; t++) {
            float best = -1e30f; int bi = 0;
            for (int u = 0; u < P2; u++)
                if (lg[u] > best) { best = lg[u]; bi = u; }   // strict > = jax tie-break
            g_idx[ib][(n*P2 + i)*TOPK + t] = bi;
            lg[bi] = -1e30f;
        }
    }
}

// ----------------------------- attention -----------------------------------
// one block per (window, head); thread = query pixel; 64 gathered KV tokens.
__global__ __launch_bounds__(256) void k_attend(int qb, int kvb, int ib, int ob)
{
    const int nwin = blockIdx.x;             // n*64+win
    const int head = blockIdx.y;
    const int n   = nwin >> 6;
    const int win = nwin & 63;
    const int tid = threadIdx.x;

    __shared__ float ks[64][32];   // rows uniform-broadcast, 128B aligned
    __shared__ float vs[64][32];
    __shared__ int sel[TOPK];
    if (tid < TOPK) sel[tid] = g_idx[ib][nwin*TOPK + tid];
    __syncthreads();

    for (int e = tid; e < 64*32; e += 256) {
        const int tkn = e >> 5, c = e & 31;
        const int sw  = sel[tkn >> 4];
        const float* pp = g_pool[kvb] + (size_t)((n*P2 + sw)*W2KV + (tkn & 15))*CKV;
        ks[tkn][c] = pp[head*DH + c];
        vs[tkn][c] = pp[QK + head*DH + c];
    }
    __syncthreads();

    const int pix = tid;
    const float* qp = g_qkv[qb] + (size_t)(nwin*W2 + pix)*QKVC + head*DH;
    u64 qd[16];
    #pragma unroll
    for (int c = 0; c < 16; c++)
        qd[c] = pack2(qp[2*c] * SCALEF, qp[2*c+1] * SCALEF);

    float lg[64];
    float mx = -1e30f;
    #pragma unroll
    for (int t = 0; t < 64; t++) {
        const u64* kr = (const u64*)ks[t];
        u64 ac = 0ull;
        #pragma unroll
        for (int c = 0; c < 16; c++) fma2(ac, qd[c], kr[c]);
        const float2 pr = unp2(ac);
        const float s = pr.x + pr.y;
        lg[t] = s;
        mx = fmaxf(mx, s);
    }
    float den = 0.f;
    #pragma unroll
    for (int t = 0; t < 64; t++) { lg[t] = expf(lg[t] - mx); den += lg[t]; }
    const float inv = 1.f / den;

    u64 o[16];
    #pragma unroll
    for (int c = 0; c < 16; c++) o[c] = 0ull;
    #pragma unroll
    for (int t = 0; t < 64; t++) {
        const u64 pd = dup2(lg[t]);
        const u64* vr = (const u64*)vs[t];
        #pragma unroll
        for (int c = 0; c < 16; c++) fma2(o[c], pd, vr[c]);
    }

    const int h = ((win >> 3) << 4) | (pix >> 4);
    const int w = ((win & 7)  << 4) | (pix & 15);
    float* op = g_att[ob] + (size_t)(((n << 7) + h)*WW + w)*DIM + head*DH;
    const u64 invd = dup2(inv);
    #pragma unroll
    for (int c = 0; c < 16; c++)
        *(u64*)(op + 2*c) = mul2(o[c], invd);
}

// --------------------------- lepe (depthwise 3x3) --------------------------
__global__ __launch_bounds__(256) void k_lepe(int vb, int ob,
    const float* __restrict__ lw, const float* __restrict__ lb)
{
    __shared__ float sw[DIM*9];
    const int p = blockIdx.x;                 // n*16384 + h*128 + w
    const int c = threadIdx.x;                // channel
    for (int e = c; e < DIM*9; e += 256) sw[e] = lw[e];
    __syncthreads();

    const int n  = p >> 14;
    const int hw = p & 16383;
    const int h  = hw >> 7;
    const int w  = hw & 127;

    float acc = g_att[ob][(size_t)p*DIM + c] + lb[c];
    #pragma unroll
    for (int dy = 0; dy < 3; dy++) {
        const int hh = h + dy - 1;
        if ((unsigned)hh >= (unsigned)HH) continue;
        #pragma unroll
        for (int dx = 0; dx < 3; dx++) {
            const int ww2 = w + dx - 1;
            if ((unsigned)ww2 >= (unsigned)WW) continue;
            const int win = ((hh >> 4) << 3) | (ww2 >> 4);
            const int pix = ((hh & 15) << 4) | (ww2 & 15);
            const float v = g_qkv[vb][(size_t)(((n << 6) | win)*W2 + pix)*QKVC + CKV + c];
            acc += v * sw[c*9 + dy*3 + dx];
        }
    }
    g_att[ob][(size_t)p*DIM + c] = acc;
}

// ----------------------------- output proj ---------------------------------
__global__ __launch_bounds__(256) void k_proj(int ob,
    const float* __restrict__ Wo, const float* __restrict__ bo,
    float* __restrict__ out)
{
    __shared__ float As[8][132];
    __shared__ float Bs[8][132];
    const int tid = threadIdx.x;
    const int tx = tid & 15, ty = tid >> 4;
    const int t0  = blockIdx.y * 128;
    const int jn0 = blockIdx.x * 128;

    const int am = tid >> 1;
    const int lk = (tid & 1) << 2;
    const float* ap = g_att[ob] + (size_t)(t0 + am) * DIM + lk;
    const float* bp = Wo + (size_t)(jn0 + am) * DIM + lk;

    u64 acc[8][4];
    #pragma unroll
    for (int i = 0; i < 8; i++)
        #pragma unroll
        for (int j = 0; j < 4; j++) acc[i][j] = 0ull;

    for (int k0 = 0; k0 < 256; k0 += 8) {
        float4 av = *(const float4*)(ap + k0);
        float4 bv = *(const float4*)(bp + k0);
        As[lk+0][am] = av.x; As[lk+1][am] = av.y; As[lk+2][am] = av.z; As[lk+3][am] = av.w;
        Bs[lk+0][am] = bv.x; Bs[lk+1][am] = bv.y; Bs[lk+2][am] = bv.z; Bs[lk+3][am] = bv.w;
        __syncthreads();
        #pragma unroll
        for (int kk = 0; kk < 8; kk++) {
            float a[8];
            *(float4*)&a[0] = *(const float4*)&As[kk][ty*8];
            *(float4*)&a[4] = *(const float4*)&As[kk][ty*8+4];
            const u64* br = (const u64*)&Bs[kk][tx*8];
            const u64 b0 = br[0], b1 = br[1], b2 = br[2], b3 = br[3];
            #pragma unroll
            for (int i = 0; i < 8; i++) {
                const u64 ad = dup2(a[i]);
                fma2(acc[i][0], ad, b0);
                fma2(acc[i][1], ad, b1);
                fma2(acc[i][2], ad, b2);
                fma2(acc[i][3], ad, b3);
            }
        }
        __syncthreads();
    }
    u64 bias[4];
    #pragma unroll
    for (int j = 0; j < 4; j++) {
        const int col = jn0 + tx*8 + j*2;
        bias[j] = pack2(bo[col], bo[col+1]);
    }
    #pragma unroll
    for (int i = 0; i < 8; i++) {
        const size_t t = (size_t)(t0 + ty*8 + i);
        #pragma unroll
        for (int j = 0; j < 4; j++) {
            const int col = jn0 + tx*8 + j*2;
            *(u64*)(out + t*DIM + col) = add2(acc[i][j], bias[j]);
        }
    }
}

// ------------------------------- launch ------------------------------------
extern "C" void kernel_launch(void* const* d_in, const int* in_sizes, int n_in,
                              void* d_out, int out_size)
{
    const float* x1   = (const float*)d_in[0];
    const float* x2   = (const float*)d_in[1];
    const float* Wqkv = (const float*)d_in[2];
    const float* bqkv = (const float*)d_in[3];
    const float* lw   = (const float*)d_in[4];
    const float* lb   = (const float*)d_in[5];
    const float* Wo   = (const float*)d_in[6];
    const float* bo   = (const float*)d_in[7];
    float* out = (float*)d_out;

    const dim3 gq(QKVC/128, TOK/128);   // (6, 512)
    k_qkv_gemm<<<gq, 256>>>(x1, Wqkv, bqkv, 0);
    k_qkv_gemm<<<gq, 256>>>(x2, Wqkv, bqkv, 1);

    k_pool<<<NB*P2, 256>>>(0);
    k_pool<<<NB*P2, 256>>>(1);

    // idx1 = route(q2w, k1w), idx2 = route(q1w, k2w)
    k_route<<<dim3(P2, NB), 64>>>(1, 0, 0);
    k_route<<<dim3(P2, NB), 64>>>(0, 1, 1);

    // out1 = attend(q2, kv1, idx1), out2 = attend(q1, kv2, idx2)
    k_attend<<<dim3(NB*P2, HEADS), 256>>>(1, 0, 0, 0);
    k_attend<<<dim3(NB*P2, HEADS), 256>>>(0, 1, 1, 1);

    // out1 += lepe(v1), out2 += lepe(v2)
    k_lepe<<<NB*HH*WW, 256>>>(0, 0, lw, lb);
    k_lepe<<<NB*HH*WW, 256>>>(1, 1, lw, lb);

    const dim3 gp(DIM/128, TOK/128);    // (2, 512)
    const size_t half = (size_t)NB*HH*WW*DIM;   // 16777216
    k_proj<<<gp, 256>>>(0, Wo, bo, out);
    k_proj<<<gp, 256>>>(1, Wo, bo, out + half);
}

// round 4
// speedup vs baseline: 1.8473x; 1.6742x over previous
#include <cuda_runtime.h>
#include <cuda_bf16.h>
#include <cstdint>

// ---------------------------------------------------------------------------
// SpatialEncoder: bi-level routing attention.
// GEMMs (QKV, proj) on mma.sync bf16 split-precision (3-product, ~1e-5 acc).
// tcgen05 is unavailable (harness targets plain sm_103); HMMA path instead.
// ---------------------------------------------------------------------------

#define NB    4
#define HH    128
#define WW    128
#define DIM   256
#define QK    256
#define CKV   512
#define QKVC  768
#define NW    8
#define P2    64
#define W2    256
#define W2KV  16
#define TOPK  4
#define HEADS 8
#define DH    32
#define TOK   (NB*P2*W2)          // 65536 window-major tokens
#define SCALEF 0.0625f

typedef unsigned long long u64;
typedef unsigned int u32;

// ---- packed f32x2 helpers --------------------------------------------------
__device__ __forceinline__ u64 pack2(float x, float y){
    u64 r; asm("mov.b64 %0,{%1,%2};" : "=l"(r) : "f"(x), "f"(y)); return r;
}
__device__ __forceinline__ u64 dup2(float x){
    u64 r; asm("mov.b64 %0,{%1,%1};" : "=l"(r) : "f"(x)); return r;
}
__device__ __forceinline__ void fma2(u64 &a, u64 b, u64 c){
    asm("fma.rn.f32x2 %0,%1,%2,%0;" : "+l"(a) : "l"(b), "l"(c));
}
__device__ __forceinline__ u64 mul2(u64 a, u64 b){
    u64 r; asm("mul.rn.f32x2 %0,%1,%2;" : "=l"(r) : "l"(a), "l"(b)); return r;
}
__device__ __forceinline__ float2 unp2(u64 v){
    float lo, hi; asm("mov.b64 {%0,%1},%2;" : "=f"(lo), "=f"(hi) : "l"(v));
    return make_float2(lo, hi);
}

__device__ __forceinline__ u32 smem_u32(const void* p){
    u32 a; asm("{ .reg .u64 t; cvta.to.shared.u64 t, %1; cvt.u32.u64 %0, t; }"
               : "=r"(a) : "l"(p));
    return a;
}

// fp32 -> (bf16 hi, bf16 lo) for a float4, packed as two u64 (4 bf16 each)
__device__ __forceinline__ void cvt4(float4 v, u64& hi, u64& lo){
    float f0=v.x, f1=v.y, f2=v.z, f3=v.w;
    __nv_bfloat16 h0=__float2bfloat16_rn(f0), h1=__float2bfloat16_rn(f1);
    __nv_bfloat16 h2=__float2bfloat16_rn(f2), h3=__float2bfloat16_rn(f3);
    unsigned short a0=__bfloat16_as_ushort(h0), a1=__bfloat16_as_ushort(h1);
    unsigned short a2=__bfloat16_as_ushort(h2), a3=__bfloat16_as_ushort(h3);
    hi = (u64)a0 | ((u64)a1<<16) | ((u64)a2<<32) | ((u64)a3<<48);
    unsigned short b0=__bfloat16_as_ushort(__float2bfloat16_rn(f0-__bfloat162float(h0)));
    unsigned short b1=__bfloat16_as_ushort(__float2bfloat16_rn(f1-__bfloat162float(h1)));
    unsigned short b2=__bfloat16_as_ushort(__float2bfloat16_rn(f2-__bfloat162float(h2)));
    unsigned short b3=__bfloat16_as_ushort(__float2bfloat16_rn(f3-__bfloat162float(h3)));
    lo = (u64)b0 | ((u64)b1<<16) | ((u64)b2<<32) | ((u64)b3<<48);
}

__device__ __forceinline__ void ldmx4(u32 addr, u32& r0, u32& r1, u32& r2, u32& r3){
    asm volatile("ldmatrix.sync.aligned.m8n8.x4.shared.b16 {%0,%1,%2,%3},[%4];"
                 : "=r"(r0),"=r"(r1),"=r"(r2),"=r"(r3) : "r"(addr));
}
__device__ __forceinline__ void mma16816(float* c, const u32* a, const u32* b){
    asm volatile("mma.sync.aligned.m16n8k16.row.col.f32.bf16.bf16.f32 "
        "{%0,%1,%2,%3},{%4,%5,%6,%7},{%8,%9},{%0,%1,%2,%3};"
        : "+f"(c[0]),"+f"(c[1]),"+f"(c[2]),"+f"(c[3])
        : "r"(a[0]),"r"(a[1]),"r"(a[2]),"r"(a[3]),"r"(b[0]),"r"(b[1]));
}

// -------- scratch -----------------------------------------------------------
__device__ float g_qkv [2][(size_t)TOK*QKVC];
__device__ float g_pool[2][NB*P2*W2KV*CKV];
__device__ float g_qwin[2][NB*P2*QK];
__device__ float g_kwin[2][NB*P2*QK];
__device__ int   g_idx [2][NB*P2*TOPK];
__device__ float g_att [2][(size_t)NB*HH*WW*DIM];

// ------------------------- HMMA split-bf16 GEMM -----------------------------
// out[t][j] = sum_c A[t][c] * W[j][c] + bias[j], K=256.
// BM=BN=128, BK=32; 8 warps (2 m x 4 n), warp tile 64x32.
// Split: D += Ah*Bh + Ah*Bl + Al*Bh  (fp32 accumulate).
#define PAD 40   // bf16 elems per smem row (80 B stride: conflict-free ldmatrix)

__global__ __launch_bounds__(256) void k_mma_gemm(
    const float* __restrict__ Aext, int a_sel,   // 0: image-map Aext, 1/2: g_att[a_sel-1]
    const float* __restrict__ Wm, const float* __restrict__ bias,
    float* __restrict__ Oext, int o_sel, int ostride)
{
    __shared__ __nv_bfloat16 sAh[128*PAD], sAl[128*PAD];
    __shared__ __nv_bfloat16 sBh[128*PAD], sBl[128*PAD];

    const int tid = threadIdx.x;
    const int wid = tid >> 5;
    const int lid = tid & 31;
    const int t0  = blockIdx.y * 128;
    const int jn0 = blockIdx.x * 128;

    const float* A = (a_sel == 0) ? Aext : g_att[a_sel - 1];
    float* O = (o_sel < 2) ? g_qkv[o_sel] : Oext;

    const int m_base = (wid >> 2) * 64;   // 0 or 64
    const int n_base = (wid & 3) * 32;    // 0,32,64,96

    // loader indices: 1024 float4 loads per operand per chunk, 4 per thread
    const int lrow = tid >> 3;            // 0..31 (+32*i)
    const int lcg  = tid & 7;             // float4 group within 32 cols

    // precompute A-row gmem base pointers for the 4 loader rows
    const float* arow[4];
    #pragma unroll
    for (int i = 0; i < 4; i++) {
        const int row = lrow + i * 32;
        if (a_sel == 0) {
            const int ltok = t0 + row;
            const int n = ltok >> 14, r = ltok & 16383;
            const int win = r >> 8, pix = r & 255;
            const int h = ((win >> 3) << 4) | (pix >> 4);
            const int w = ((win & 7) << 4) | (pix & 15);
            arow[i] = A + ((size_t)(((n << 7) + h) << 7) + w) * DIM + lcg * 4;
        } else {
            arow[i] = A + (size_t)(t0 + row) * DIM + lcg * 4;
        }
    }
    const float* brow[4];
    #pragma unroll
    for (int i = 0; i < 4; i++)
        brow[i] = Wm + (size_t)(jn0 + lrow + i * 32) * 256 + lcg * 4;

    const u32 uAh = smem_u32(sAh), uAl = smem_u32(sAl);
    const u32 uBh = smem_u32(sBh), uBl = smem_u32(sBl);

    // ldmatrix lane address components
    const int a_r  = lid & 15;            // m within 16
    const int a_kh = lid >> 4;            // k half
    const int b_r  = (lid & 7) | ((lid >> 4) << 3);  // n within 16
    const int b_kh = (lid >> 3) & 1;

    float acc[4][4][4];
    #pragma unroll
    for (int mt = 0; mt < 4; mt++)
        #pragma unroll
        for (int nt = 0; nt < 4; nt++)
            #pragma unroll
            for (int r = 0; r < 4; r++) acc[mt][nt][r] = 0.f;

    for (int k0 = 0; k0 < 256; k0 += 32) {
        // ---- fill smem (fp32 -> bf16 hi/lo) ----
        __syncthreads();
        #pragma unroll
        for (int i = 0; i < 4; i++) {
            const int row = lrow + i * 32;
            float4 va = *(const float4*)(arow[i] + k0);
            float4 vb = *(const float4*)(brow[i] + k0);
            u64 hi, lo;
            cvt4(va, hi, lo);
            const int off = row * PAD + lcg * 4;
            *(u64*)(sAh + off) = hi;  *(u64*)(sAl + off) = lo;
            cvt4(vb, hi, lo);
            *(u64*)(sBh + off) = hi;  *(u64*)(sBl + off) = lo;
        }
        __syncthreads();

        // ---- mma over 2 k16 slices ----
        #pragma unroll
        for (int s = 0; s < 2; s++) {
            const int koff = s * 16;
            u32 ah[4][4], al[4][4], bh[4][2], bl[4][2];
            #pragma unroll
            for (int mt = 0; mt < 4; mt++) {
                const u32 eoff = (u32)((m_base + mt*16 + a_r) * PAD + koff + a_kh*8) * 2;
                ldmx4(uAh + eoff, ah[mt][0], ah[mt][1], ah[mt][2], ah[mt][3]);
                ldmx4(uAl + eoff, al[mt][0], al[mt][1], al[mt][2], al[mt][3]);
            }
            #pragma unroll
            for (int p = 0; p < 2; p++) {
                const u32 eoff = (u32)((n_base + p*16 + b_r) * PAD + koff + b_kh*8) * 2;
                ldmx4(uBh + eoff, bh[2*p][0], bh[2*p][1], bh[2*p+1][0], bh[2*p+1][1]);
                ldmx4(uBl + eoff, bl[2*p][0], bl[2*p][1], bl[2*p+1][0], bl[2*p+1][1]);
            }
            #pragma unroll
            for (int mt = 0; mt < 4; mt++)
                #pragma unroll
                for (int nt = 0; nt < 4; nt++) {
                    mma16816(acc[mt][nt], ah[mt], bh[nt]);
                    mma16816(acc[mt][nt], ah[mt], bl[nt]);
                    mma16816(acc[mt][nt], al[mt], bh[nt]);
                }
        }
    }

    // ---- epilogue: bias + direct stores ----
    const int qr = lid >> 2;              // 0..7
    const int qc = (lid & 3) * 2;
    #pragma unroll
    for (int mt = 0; mt < 4; mt++) {
        const int row0 = t0 + m_base + mt*16 + qr;
        #pragma unroll
        for (int nt = 0; nt < 4; nt++) {
            const int col = jn0 + n_base + nt*8 + qc;
            const float b0 = bias[col], b1 = bias[col+1];
            float2 v0 = make_float2(acc[mt][nt][0] + b0, acc[mt][nt][1] + b1);
            float2 v1 = make_float2(acc[mt][nt][2] + b0, acc[mt][nt][3] + b1);
            *(float2*)(O + (size_t)row0 * ostride + col)       = v0;
            *(float2*)(O + (size_t)(row0+8) * ostride + col)   = v1;
        }
    }
}

// ------------------------------ pooling ------------------------------------
__global__ __launch_bounds__(256) void k_pool(int b)
{
    const int nwin = blockIdx.x;
    const int tid = threadIdx.x;
    const float* base = g_qkv[b] + (size_t)nwin * W2 * QKVC;

    float qs = 0.f, ks = 0.f;
    for (int p = 0; p < W2; p++) {
        qs += base[(size_t)p*QKVC + tid];
        ks += base[(size_t)p*QKVC + QK + tid];
    }
    g_qwin[b][nwin*QK + tid] = qs * (1.f/256.f);
    g_kwin[b][nwin*QK + tid] = ks * (1.f/256.f);

    for (int e = tid; e < W2KV*CKV; e += 256) {
        const int s  = e >> 9;
        const int cc = e & 511;
        const int py0 = (s >> 2) << 2, px0 = (s & 3) << 2;
        float acc = 0.f;
        #pragma unroll
        for (int i = 0; i < 4; i++)
            #pragma unroll
            for (int j = 0; j < 4; j++)
                acc += base[(size_t)((py0+i)*16 + px0+j)*QKVC + QK + cc];
        g_pool[b][(size_t)(nwin*W2KV + s)*CKV + cc] = acc * (1.f/16.f);
    }
}

// ------------------------------ routing ------------------------------------
__global__ void k_route(int qb, int kb, int ib)
{
    const int i = blockIdx.x;
    const int n = blockIdx.y;
    const int j = threadIdx.x;
    const float* qp = g_qwin[qb] + (size_t)(n*P2 + i)*QK;
    const float* kp = g_kwin[kb] + (size_t)(n*P2 + j)*QK;
    float s = 0.f;
    for (int c = 0; c < QK; c++) s += qp[c]*kp[c];
    s *= SCALEF;
    if (j == i) s = 1.0f;
    __shared__ float lg[P2];
    lg[j] = s;
    __syncthreads();
    if (j == 0) {
        #pragma unroll
        for (int t = 0; t < TOPK; t++) {
            float best = -1e30f; int bi = 0;
            for (int u = 0; u < P2; u++)
                if (lg[u] > best) { best = lg[u]; bi = u; }
            g_idx[ib][(n*P2 + i)*TOPK + t] = bi;
            lg[bi] = -1e30f;
        }
    }
}

// ----------------------------- attention -----------------------------------
__global__ __launch_bounds__(256) void k_attend(int qb, int kvb, int ib, int ob)
{
    const int nwin = blockIdx.x;
    const int head = blockIdx.y;
    const int n   = nwin >> 6;
    const int win = nwin & 63;
    const int tid = threadIdx.x;

    __shared__ float ks[64][32];
    __shared__ float vs[64][32];
    __shared__ int sel[TOPK];
    if (tid < TOPK) sel[tid] = g_idx[ib][nwin*TOPK + tid];
    __syncthreads();

    for (int e = tid; e < 64*32; e += 256) {
        const int tkn = e >> 5, c = e & 31;
        const int sw  = sel[tkn >> 4];
        const float* pp = g_pool[kvb] + (size_t)((n*P2 + sw)*W2KV + (tkn & 15))*CKV;
        ks[tkn][c] = pp[head*DH + c];
        vs[tkn][c] = pp[QK + head*DH + c];
    }
    __syncthreads();

    const int pix = tid;
    const float* qp = g_qkv[qb] + (size_t)(nwin*W2 + pix)*QKVC + head*DH;
    u64 qd[16];
    #pragma unroll
    for (int c = 0; c < 16; c++)
        qd[c] = pack2(qp[2*c] * SCALEF, qp[2*c+1] * SCALEF);

    float lg[64];
    float mx = -1e30f;
    #pragma unroll
    for (int t = 0; t < 64; t++) {
        const u64* kr = (const u64*)ks[t];
        u64 ac = 0ull;
        #pragma unroll
        for (int c = 0; c < 16; c++) fma2(ac, qd[c], kr[c]);
        const float2 pr = unp2(ac);
        const float s = pr.x + pr.y;
        lg[t] = s;
        mx = fmaxf(mx, s);
    }
    float den = 0.f;
    #pragma unroll
    for (int t = 0; t < 64; t++) { lg[t] = expf(lg[t] - mx); den += lg[t]; }
    const float inv = 1.f / den;

    u64 o[16];
    #pragma unroll
    for (int c = 0; c < 16; c++) o[c] = 0ull;
    #pragma unroll
    for (int t = 0; t < 64; t++) {
        const u64 pd = dup2(lg[t]);
        const u64* vr = (const u64*)vs[t];
        #pragma unroll
        for (int c = 0; c < 16; c++) fma2(o[c], pd, vr[c]);
    }

    const int h = ((win >> 3) << 4) | (pix >> 4);
    const int w = ((win & 7)  << 4) | (pix & 15);
    float* op = g_att[ob] + (size_t)(((n << 7) + h)*WW + w)*DIM + head*DH;
    const u64 invd = dup2(inv);
    #pragma unroll
    for (int c = 0; c < 16; c++)
        *(u64*)(op + 2*c) = mul2(o[c], invd);
}

// --------------------------- lepe (depthwise 3x3) --------------------------
__global__ __launch_bounds__(256) void k_lepe(int vb, int ob,
    const float* __restrict__ lw, const float* __restrict__ lb)
{
    __shared__ float sw[DIM*9];
    const int p = blockIdx.x;
    const int c = threadIdx.x;
    for (int e = c; e < DIM*9; e += 256) sw[e] = lw[e];
    __syncthreads();

    const int n  = p >> 14;
    const int hw = p & 16383;
    const int h  = hw >> 7;
    const int w  = hw & 127;

    float acc = g_att[ob][(size_t)p*DIM + c] + lb[c];
    #pragma unroll
    for (int dy = 0; dy < 3; dy++) {
        const int hh = h + dy - 1;
        if ((unsigned)hh >= (unsigned)HH) continue;
        #pragma unroll
        for (int dx = 0; dx < 3; dx++) {
            const int ww2 = w + dx - 1;
            if ((unsigned)ww2 >= (unsigned)WW) continue;
            const int win = ((hh >> 4) << 3) | (ww2 >> 4);
            const int pix = ((hh & 15) << 4) | (ww2 & 15);
            const float v = g_qkv[vb][(size_t)(((n << 6) | win)*W2 + pix)*QKVC + CKV + c];
            acc += v * sw[c*9 + dy*3 + dx];
        }
    }
    g_att[ob][(size_t)p*DIM + c] = acc;
}

// ------------------------------- launch ------------------------------------
extern "C" void kernel_launch(void* const* d_in, const int* in_sizes, int n_in,
                              void* d_out, int out_size)
{
    const float* x1   = (const float*)d_in[0];
    const float* x2   = (const float*)d_in[1];
    const float* Wqkv = (const float*)d_in[2];
    const float* bqkv = (const float*)d_in[3];
    const float* lw   = (const float*)d_in[4];
    const float* lb   = (const float*)d_in[5];
    const float* Wo   = (const float*)d_in[6];
    const float* bo   = (const float*)d_in[7];
    float* out = (float*)d_out;

    const dim3 gq(QKVC/128, TOK/128);   // (6, 512)
    k_mma_gemm<<<gq, 256>>>(x1, 0, Wqkv, bqkv, nullptr, 0, QKVC);
    k_mma_gemm<<<gq, 256>>>(x2, 0, Wqkv, bqkv, nullptr, 1, QKVC);

    k_pool<<<NB*P2, 256>>>(0);
    k_pool<<<NB*P2, 256>>>(1);

    k_route<<<dim3(P2, NB), 64>>>(1, 0, 0);
    k_route<<<dim3(P2, NB), 64>>>(0, 1, 1);

    k_attend<<<dim3(NB*P2, HEADS), 256>>>(1, 0, 0, 0);
    k_attend<<<dim3(NB*P2, HEADS), 256>>>(0, 1, 1, 1);

    k_lepe<<<NB*HH*WW, 256>>>(0, 0, lw, lb);
    k_lepe<<<NB*HH*WW, 256>>>(1, 1, lw, lb);

    const dim3 gp(DIM/128, TOK/128);    // (2, 512)
    const size_t half = (size_t)NB*HH*WW*DIM;
    k_mma_gemm<<<gp, 256>>>(nullptr, 1, Wo, bo, out, 2, DIM);
    k_mma_gemm<<<gp, 256>>>(nullptr, 2, Wo, bo, out + half, 2, DIM);
}